// round 15
// baseline (speedup 1.0000x reference)
#include <cuda_runtime.h>
#include <cstdint>

// Problem constants
#define Bn   4
#define Sn   1024
#define INn  6
#define Dn   512
#define Hn   8
#define Ln   4
#define Fn   2048
#define DKn  64
#define BSn  (Bn * Sn)   // 4096 tokens
#define RR   ((long long)BSn * Dn)
#define PGRID 444        // 148 SMs x 3 CTAs

// ---------------- scratch ----------------
__device__ float gbuf_x  [2 * BSn * Dn];
__device__ float gbuf_c  [2 * BSn * Dn];
__device__ float gbuf_qkv[6 * BSn * Dn];
__device__ float gbuf_ctx[2 * BSn * Dn];
__device__ float gbuf_o  [2 * BSn * Dn];
__device__ float gbuf_ffh[2 * BSn * Fn];
__device__ float gbuf_fused[Bn * 2 * Dn];
// tf32-pre-rounded weights
__device__ float gbuf_wm [Ln * 4 * 4 * Dn * Dn];
__device__ float gbuf_wf1[Ln * 2 * Dn * Fn];
__device__ float gbuf_wf2[Ln * 2 * Fn * Dn];

__device__ __forceinline__ float to_tf32(float x) {
    float r;
    asm("cvt.rna.tf32.f32 %0, %1;" : "=f"(r) : "f"(x));
    return r;
}

__device__ __forceinline__ float fast_ex2(float x) {
    float r;
    asm("ex2.approx.ftz.f32 %0, %1;" : "=f"(r) : "f"(x));
    return r;
}

__device__ __forceinline__ void mma_tf32(float* d, const uint32_t* a, const uint32_t* b) {
    asm volatile(
        "mma.sync.aligned.m16n8k8.row.col.f32.tf32.tf32.f32 "
        "{%0,%1,%2,%3}, {%4,%5,%6,%7}, {%8,%9}, {%0,%1,%2,%3};\n"
        : "+f"(d[0]), "+f"(d[1]), "+f"(d[2]), "+f"(d[3])
        : "r"(a[0]), "r"(a[1]), "r"(a[2]), "r"(a[3]),
          "r"(b[0]), "r"(b[1]));
}

#define CP_ASYNC16(dst, src) \
    asm volatile("cp.async.cg.shared.global [%0], [%1], 16;" :: "r"(dst), "l"(src))
#define CP_COMMIT() asm volatile("cp.async.commit_group;")

// ---------------- weight pre-round to tf32 ----------------
__global__ void cvt_tf32_kernel(const float4* __restrict__ in, float4* __restrict__ out, int n4)
{
    int i = blockIdx.x * 256 + threadIdx.x;
    if (i < n4) {
        float4 t = in[i];
        t.x = to_tf32(t.x); t.y = to_tf32(t.y);
        t.z = to_tf32(t.z); t.w = to_tf32(t.w);
        out[i] = t;
    }
}

// ---------------- embedding, both channels in one launch ----------------
__global__ void embed_kernel(const float* __restrict__ inL, const float* __restrict__ inR,
                             const float* __restrict__ WlP, const float* __restrict__ blP,
                             const float* __restrict__ WrP, const float* __restrict__ brP,
                             const float* __restrict__ pe, float* __restrict__ out)
{
    int idx = blockIdx.x * 256 + threadIdx.x;   // < 2*BSn*Dn
    int chan = (idx >= BSn * Dn) ? 1 : 0;
    int id = idx - chan * BSn * Dn;
    const float* in   = chan ? inR : inL;
    const float* W    = chan ? WrP : WlP;
    const float* bias = chan ? brP : blP;
    int d = id & (Dn - 1);
    int t = id >> 9;
    int s = t & (Sn - 1);
    float acc = bias[d] + pe[s * Dn + d];
#pragma unroll
    for (int i = 0; i < INn; i++)
        acc += in[t * INn + i] * W[i * Dn + d];
    out[idx] = to_tf32(acc);
}

// ---------------- TF32 GEMM, persistent, 128x128x32, 4 warps x (64x64), 2-stage, 3 CTA/SM ----------------
#define BM 128
#define BN 128
#define BK 32
#define APAD 36
#define BPAD 136
#define A_STG (BM * APAD)
#define B_STG (BK * BPAD)
#define TGEMM_SMEM ((2 * A_STG + 2 * B_STG) * 4)   // 71680 bytes

template <bool RELU, bool RES>
__global__ __launch_bounds__(128, 3)
void tgemm(const float* __restrict__ A0, const float* __restrict__ Bm0,
           const float* __restrict__ bias0, float* __restrict__ C0,
           const float* __restrict__ Rres0,
           int K, int lda, int ldb, int ldc, int zdiv,
           long long aQ0, long long aKV0, long long aQ1, long long aKV1,
           long long sBb, long long sBi, long long sBiasB, long long sBiasI,
           long long sC,
           int gx, int gy, int total)
{
    extern __shared__ float sm[];
    float* As = sm;
    float* Bs = sm + 2 * A_STG;

    const int tid = threadIdx.x;
    const int lane = tid & 31;
    const int warp = tid >> 5;
    const int wm = (warp >> 1) * 64;
    const int wn = (warp & 1) * 64;
    const int g = lane >> 2;
    const int c = lane & 3;

    const int a_kc4 = tid & 7;
    const int a_row0 = tid >> 3;
    const int b_c4 = tid & 31;
    const int b_krow = tid >> 5;

    const int NT = K / BK;
    const int gxy = gx * gy;

    for (int tile = blockIdx.x; tile < total; tile += gridDim.x) {
        const int z = tile / gxy;
        const int rem = tile - z * gxy;
        const int by = rem / gx;
        const int bx = rem - by * gx;
        const int bm = by * BM;
        const int bn = bx * BN;

        const int zb = z / zdiv, zi = z - zb * zdiv;
        const float* A = A0 + ((zb == 0) ? (zi == 0 ? aQ0 : aKV0) : (zi == 0 ? aQ1 : aKV1));
        const float* Bm = Bm0 + zb * sBb + zi * sBi;
        const float* bias = bias0 + zb * sBiasB + zi * sBiasI;
        float* C = C0 + (long long)z * sC;
        const float* Rres = RES ? (Rres0 + (long long)z * sC) : nullptr;

        float acc[4][8][4];
#pragma unroll
        for (int i = 0; i < 4; i++)
#pragma unroll
            for (int j = 0; j < 8; j++)
#pragma unroll
                for (int q = 0; q < 4; q++) acc[i][j][q] = 0.f;

        auto prefetch = [&](int t) {
            const int k0 = t * BK;
            const int stage = t & 1;
            float* Ad = As + stage * A_STG;
            float* Bd = Bs + stage * B_STG;
#pragma unroll
            for (int v = 0; v < 8; v++) {
                int r = a_row0 + v * 16;
                uint32_t d = (uint32_t)__cvta_generic_to_shared(&Ad[r * APAD + a_kc4 * 4]);
                CP_ASYNC16(d, &A[(long long)(bm + r) * lda + k0 + a_kc4 * 4]);
            }
#pragma unroll
            for (int v = 0; v < 8; v++) {
                int r = b_krow + v * 4;
                uint32_t d = (uint32_t)__cvta_generic_to_shared(&Bd[r * BPAD + b_c4 * 4]);
                CP_ASYNC16(d, &Bm[(long long)(k0 + r) * ldb + bn + b_c4 * 4]);
            }
            CP_COMMIT();
        };

        prefetch(0);
        prefetch(1);

        for (int t = 0; t < NT; t++) {
            if (t + 1 < NT) asm volatile("cp.async.wait_group 1;");
            else            asm volatile("cp.async.wait_group 0;");
            __syncthreads();

            const float* Ab = As + (t & 1) * A_STG;
            const float* Bb = Bs + (t & 1) * B_STG;
#pragma unroll
            for (int kk = 0; kk < BK; kk += 8) {
                uint32_t afr[4][4];
#pragma unroll
                for (int i = 0; i < 4; i++) {
                    int m = wm + i * 16;
                    afr[i][0] = *(const uint32_t*)&Ab[(m + g) * APAD + kk + c];
                    afr[i][1] = *(const uint32_t*)&Ab[(m + g + 8) * APAD + kk + c];
                    afr[i][2] = *(const uint32_t*)&Ab[(m + g) * APAD + kk + c + 4];
                    afr[i][3] = *(const uint32_t*)&Ab[(m + g + 8) * APAD + kk + c + 4];
                }
                uint32_t bfr[8][2];
#pragma unroll
                for (int j = 0; j < 8; j++) {
                    int n = wn + j * 8 + g;
                    bfr[j][0] = *(const uint32_t*)&Bb[(kk + c) * BPAD + n];
                    bfr[j][1] = *(const uint32_t*)&Bb[(kk + c + 4) * BPAD + n];
                }
#pragma unroll
                for (int i = 0; i < 4; i++)
#pragma unroll
                    for (int j = 0; j < 8; j++)
                        mma_tf32(acc[i][j], afr[i], bfr[j]);
            }

            __syncthreads();               // stage t&1 free for t+2
            if (t + 2 < NT) prefetch(t + 2);
        }

#pragma unroll
        for (int i = 0; i < 4; i++) {
            int row0 = bm + wm + i * 16 + g;
            int row1 = row0 + 8;
#pragma unroll
            for (int j = 0; j < 8; j++) {
                int col = bn + wn + j * 8 + 2 * c;
                float bv0 = bias[col];
                float bv1 = bias[col + 1];
                float2 o0, o1;
                o0.x = acc[i][j][0] + bv0;
                o0.y = acc[i][j][1] + bv1;
                o1.x = acc[i][j][2] + bv0;
                o1.y = acc[i][j][3] + bv1;
                if (RELU) {
                    o0.x = fmaxf(o0.x, 0.f); o0.y = fmaxf(o0.y, 0.f);
                    o1.x = fmaxf(o1.x, 0.f); o1.y = fmaxf(o1.y, 0.f);
                }
                if (RES) {
                    float2 r0v = *(const float2*)&Rres[(long long)row0 * ldc + col];
                    float2 r1v = *(const float2*)&Rres[(long long)row1 * ldc + col];
                    o0.x += r0v.x; o0.y += r0v.y;
                    o1.x += r1v.x; o1.y += r1v.y;
                }
                o0.x = to_tf32(o0.x); o0.y = to_tf32(o0.y);
                o1.x = to_tf32(o1.x); o1.y = to_tf32(o1.y);
                *(float2*)&C[(long long)row0 * ldc + col] = o0;
                *(float2*)&C[(long long)row1 * ldc + col] = o1;
            }
        }
        __syncthreads();   // protect smem stages before next tile's prefetch
    }
}

// ---------------- flash attention: 4 warps x 32 q-rows, deferred softmax-sum reduction ----------------
#define FA_SMEM_BYTES ((128*68 + 2*64*68 + 2*64*72) * 4)

__global__ __launch_bounds__(128, 2)
void flash_kernel(const float* __restrict__ qkv, float* __restrict__ ctx)
{
    extern __shared__ float sm[];
    float* Qs = sm;                      // [128][68]
    float* Ks = sm + 128 * 68;           // [2][64][68]
    float* Vs = Ks + 2 * 64 * 68;        // [2][64][72]

    const int qt = blockIdx.x, bh = blockIdx.y, zb = blockIdx.z;
    const int b = bh >> 3, h = bh & 7;
    const float* Qg = qkv + (long long)zb * 3 * RR;
    const float* Kg = Qg + RR;
    const float* Vg = Qg + 2 * RR;
    const long long tq  = (long long)b * Sn + qt * 128;
    const long long tk0 = (long long)b * Sn;
    const int hc = h * DKn;

    const int tid = threadIdx.x, lane = tid & 31, warp = tid >> 5;
    const int g = lane >> 2, c = lane & 3;
    const int wrow = warp * 32;
    const int src0 = (lane & 28) | (c >> 1);
    const int src2 = src0 + 2;
    const bool codd = (c & 1) != 0;

    const float QS = 0.125f * 1.4426950408889634f;
#pragma unroll
    for (int i = 0; i < 16; i++) {
        int f = tid + i * 128, row = f >> 4, c4 = f & 15;
        float4 t = *(const float4*)&Qg[(tq + row) * Dn + hc + c4 * 4];
        t.x = to_tf32(t.x * QS); t.y = to_tf32(t.y * QS);
        t.z = to_tf32(t.z * QS); t.w = to_tf32(t.w * QS);
        *(float4*)&Qs[row * 68 + c4 * 4] = t;
    }

    auto prefetch = [&](int t, int buf) {
        const long long rbase = tk0 + t * 64;
#pragma unroll
        for (int i = 0; i < 8; i++) {
            int f = tid + i * 128, r = f >> 4, c4 = f & 15;
            const float* gk = &Kg[(rbase + r) * Dn + hc + c4 * 4];
            const float* gv = &Vg[(rbase + r) * Dn + hc + c4 * 4];
            uint32_t sk = (uint32_t)__cvta_generic_to_shared(&Ks[(buf * 64 + r) * 68 + c4 * 4]);
            uint32_t sv = (uint32_t)__cvta_generic_to_shared(&Vs[(buf * 64 + r) * 72 + c4 * 4]);
            CP_ASYNC16(sk, gk);
            CP_ASYNC16(sv, gv);
        }
        CP_COMMIT();
    };

    prefetch(0, 0);
    prefetch(1, 1);

    float l[2][2] = {{0.f, 0.f}, {0.f, 0.f}};
    float oacc[2][8][4];
#pragma unroll
    for (int st = 0; st < 2; st++)
#pragma unroll
        for (int j = 0; j < 8; j++)
#pragma unroll
            for (int q = 0; q < 4; q++) oacc[st][j][q] = 0.f;

    for (int t = 0; t < Sn / 64; t++) {
        if (t < Sn / 64 - 1) asm volatile("cp.async.wait_group 1;");
        else                 asm volatile("cp.async.wait_group 0;");
        __syncthreads();

        const float* Kb = &Ks[(t & 1) * 64 * 68];
        const float* Vb = &Vs[(t & 1) * 64 * 72];

        float sacc[2][8][4];
#pragma unroll
        for (int st = 0; st < 2; st++)
#pragma unroll
            for (int j = 0; j < 8; j++)
#pragma unroll
                for (int q = 0; q < 4; q++) sacc[st][j][q] = 0.f;
#pragma unroll
        for (int s = 0; s < 8; s++) {
            uint32_t af[2][4];
#pragma unroll
            for (int st = 0; st < 2; st++) {
                int r = wrow + st * 16;
                af[st][0] = *(const uint32_t*)&Qs[(r + g) * 68 + s * 8 + c];
                af[st][1] = *(const uint32_t*)&Qs[(r + g + 8) * 68 + s * 8 + c];
                af[st][2] = *(const uint32_t*)&Qs[(r + g) * 68 + s * 8 + c + 4];
                af[st][3] = *(const uint32_t*)&Qs[(r + g + 8) * 68 + s * 8 + c + 4];
            }
#pragma unroll
            for (int j = 0; j < 8; j++) {
                uint32_t bf[2];
                bf[0] = *(const uint32_t*)&Kb[(j * 8 + g) * 68 + s * 8 + c];
                bf[1] = *(const uint32_t*)&Kb[(j * 8 + g) * 68 + s * 8 + c + 4];
                mma_tf32(sacc[0][j], af[0], bf);
                mma_tf32(sacc[1][j], af[1], bf);
            }
        }

#pragma unroll
        for (int st = 0; st < 2; st++) {
            float ps0 = 0.f, ps1 = 0.f;
#pragma unroll
            for (int j = 0; j < 8; j++) {
                sacc[st][j][0] = fast_ex2(sacc[st][j][0]);
                sacc[st][j][1] = fast_ex2(sacc[st][j][1]);
                sacc[st][j][2] = fast_ex2(sacc[st][j][2]);
                sacc[st][j][3] = fast_ex2(sacc[st][j][3]);
                ps0 += sacc[st][j][0] + sacc[st][j][1];
                ps1 += sacc[st][j][2] + sacc[st][j][3];
            }
            l[st][0] += ps0;
            l[st][1] += ps1;
        }

#pragma unroll
        for (int s = 0; s < 8; s++) {
            uint32_t afp[2][4];
#pragma unroll
            for (int st = 0; st < 2; st++) {
                float v0 = __shfl_sync(0xffffffffu, sacc[st][s][0], src0);
                float v1 = __shfl_sync(0xffffffffu, sacc[st][s][1], src0);
                float v2 = __shfl_sync(0xffffffffu, sacc[st][s][2], src0);
                float v3 = __shfl_sync(0xffffffffu, sacc[st][s][3], src0);
                float w0 = __shfl_sync(0xffffffffu, sacc[st][s][0], src2);
                float w1 = __shfl_sync(0xffffffffu, sacc[st][s][1], src2);
                float w2 = __shfl_sync(0xffffffffu, sacc[st][s][2], src2);
                float w3 = __shfl_sync(0xffffffffu, sacc[st][s][3], src2);
                afp[st][0] = __float_as_uint(to_tf32(codd ? v1 : v0));
                afp[st][1] = __float_as_uint(to_tf32(codd ? v3 : v2));
                afp[st][2] = __float_as_uint(to_tf32(codd ? w1 : w0));
                afp[st][3] = __float_as_uint(to_tf32(codd ? w3 : w2));
            }
#pragma unroll
            for (int j = 0; j < 8; j++) {
                uint32_t bf[2];
                bf[0] = *(const uint32_t*)&Vb[(s * 8 + c) * 72 + j * 8 + g];
                bf[1] = *(const uint32_t*)&Vb[(s * 8 + c + 4) * 72 + j * 8 + g];
                mma_tf32(oacc[0][j], afp[0], bf);
                mma_tf32(oacc[1][j], afp[1], bf);
            }
        }

        __syncthreads();
        if (t + 2 < Sn / 64) prefetch(t + 2, t & 1);
    }

#pragma unroll
    for (int st = 0; st < 2; st++) {
#pragma unroll
        for (int hh = 0; hh < 2; hh++) {
            l[st][hh] += __shfl_xor_sync(0xffffffffu, l[st][hh], 1);
            l[st][hh] += __shfl_xor_sync(0xffffffffu, l[st][hh], 2);
        }
    }

    float* Co = ctx + (long long)zb * RR;
#pragma unroll
    for (int st = 0; st < 2; st++) {
        float inv0 = 1.f / l[st][0], inv1 = 1.f / l[st][1];
        int r = wrow + st * 16;
#pragma unroll
        for (int j = 0; j < 8; j++) {
            float2 o01, o23;
            o01.x = to_tf32(oacc[st][j][0] * inv0); o01.y = to_tf32(oacc[st][j][1] * inv0);
            o23.x = to_tf32(oacc[st][j][2] * inv1); o23.y = to_tf32(oacc[st][j][3] * inv1);
            *(float2*)&Co[(tq + r + g) * Dn + hc + j * 8 + 2 * c] = o01;
            *(float2*)&Co[(tq + r + g + 8) * Dn + hc + j * 8 + 2 * c] = o23;
        }
    }
}

// ---------------- layernorm (input already contains residual sum) ----------------
__global__ void ln_kernel(const float* __restrict__ x,
                          const float* __restrict__ g, const float* __restrict__ be,
                          float* __restrict__ out)
{
    long long row = blockIdx.x;
    const int chan = (row >= BSn) ? 1 : 0;
    const float* gp = g + chan * Dn;
    const float* bp = be + chan * Dn;
    const float* xp = x + row * Dn;
    int t = threadIdx.x;
    int lane = t & 31, warp = t >> 5;
    float v[4]; float s = 0.f, s2 = 0.f;
#pragma unroll
    for (int i = 0; i < 4; i++) {
        int cc = t + i * 128;
        v[i] = xp[cc];
        s += v[i]; s2 += v[i] * v[i];
    }
#pragma unroll
    for (int o = 16; o > 0; o >>= 1) {
        s  += __shfl_xor_sync(0xffffffffu, s,  o);
        s2 += __shfl_xor_sync(0xffffffffu, s2, o);
    }
    __shared__ float ws[4], ws2[4];
    if (lane == 0) { ws[warp] = s; ws2[warp] = s2; }
    __syncthreads();
    float S  = ws[0] + ws[1] + ws[2] + ws[3];
    float S2 = ws2[0] + ws2[1] + ws2[2] + ws2[3];
    float mean = S * (1.f / Dn);
    float var  = S2 * (1.f / Dn) - mean * mean;
    float rstd = rsqrtf(var + 1e-5f);
    float* op = out + row * Dn;
#pragma unroll
    for (int i = 0; i < 4; i++) {
        int cc = t + i * 128;
        op[cc] = to_tf32((v[i] - mean) * rstd * gp[cc] + bp[cc]);
    }
}

// ---------------- pool (parallel over S) + heads ----------------
__global__ void pool_kernel(const float* __restrict__ x, float* __restrict__ fused)
{
    __shared__ float red[4][64];
    int blk = blockIdx.x;
    int bc = blk >> 3;
    int slab = blk & 7;
    int b = bc >> 1, chan = bc & 1;
    int t = threadIdx.x;
    int col = (t & 63) + slab * 64;
    int rg = t >> 6;
    const float* src = x + (long long)chan * RR + (long long)b * Sn * Dn + col;
    float s = 0.f;
    for (int r = rg * 256; r < (rg + 1) * 256; r++)
        s += src[(long long)r * Dn];
    red[rg][t & 63] = s;
    __syncthreads();
    if (rg == 0) {
        float tot = red[0][t] + red[1][t] + red[2][t] + red[3][t];
        fused[b * 2 * Dn + chan * Dn + col] = tot * (1.f / Sn);
    }
}

__global__ void head_kernel(const float* __restrict__ fused,
                            const float* __restrict__ w1, const float* __restrict__ b1,
                            const float* __restrict__ w2, const float* __restrict__ b2,
                            float* __restrict__ out)
{
    __shared__ float sf[2 * Dn];
    int b = blockIdx.x, t = threadIdx.x;
    sf[t]      = fused[b * 2 * Dn + t];
    sf[t + Dn] = fused[b * 2 * Dn + t + Dn];
    __syncthreads();
    float h = b1[t];
    for (int k = 0; k < 2 * Dn; k++)
        h += sf[k] * w1[k * Dn + t];
    h = fmaxf(h, 0.f);
    __shared__ float r0[512], r1[512];
    r0[t] = h * w2[t * 2 + 0];
    r1[t] = h * w2[t * 2 + 1];
    __syncthreads();
#pragma unroll
    for (int o = 256; o > 0; o >>= 1) {
        if (t < o) { r0[t] += r0[t + o]; r1[t] += r1[t + o]; }
        __syncthreads();
    }
    if (t == 0) {
        out[b * 2 + 0] = r0[0] + b2[0];
        out[b * 2 + 1] = r1[0] + b2[1];
    }
}

static inline int pg(int total) { return total < PGRID ? total : PGRID; }

extern "C" void kernel_launch(void* const* d_in, const int* in_sizes, int n_in,
                              void* d_out, int out_size)
{
    const float* left_wrist  = (const float*)d_in[0];
    const float* right_wrist = (const float*)d_in[1];
    const float* Wl = (const float*)d_in[2];
    const float* bl = (const float*)d_in[3];
    const float* Wr = (const float*)d_in[4];
    const float* br = (const float*)d_in[5];
    const float* pe = (const float*)d_in[6];
    const float* mha_w    = (const float*)d_in[7];
    const float* mha_b    = (const float*)d_in[8];
    const float* mha_ln_g = (const float*)d_in[9];
    const float* mha_ln_b = (const float*)d_in[10];
    const float* ff_w1    = (const float*)d_in[11];
    const float* ff_b1    = (const float*)d_in[12];
    const float* ff_w2    = (const float*)d_in[13];
    const float* ff_b2    = (const float*)d_in[14];
    const float* ff_ln_g  = (const float*)d_in[15];
    const float* ff_ln_b  = (const float*)d_in[16];
    const float* h1_w1 = (const float*)d_in[17];
    const float* h1_b1 = (const float*)d_in[18];
    const float* h1_w2 = (const float*)d_in[19];
    const float* h1_b2 = (const float*)d_in[20];
    const float* h2_w1 = (const float*)d_in[21];
    const float* h2_b1 = (const float*)d_in[22];
    const float* h2_w2 = (const float*)d_in[23];
    const float* h2_b2 = (const float*)d_in[24];
    float* out = (float*)d_out;

    float *pX, *pC, *pQKV, *pCtx, *pO, *pFfh, *pFused, *pWm, *pWf1, *pWf2;
    cudaGetSymbolAddress((void**)&pX,    gbuf_x);
    cudaGetSymbolAddress((void**)&pC,    gbuf_c);
    cudaGetSymbolAddress((void**)&pQKV,  gbuf_qkv);
    cudaGetSymbolAddress((void**)&pCtx,  gbuf_ctx);
    cudaGetSymbolAddress((void**)&pO,    gbuf_o);
    cudaGetSymbolAddress((void**)&pFfh,  gbuf_ffh);
    cudaGetSymbolAddress((void**)&pFused, gbuf_fused);
    cudaGetSymbolAddress((void**)&pWm,   gbuf_wm);
    cudaGetSymbolAddress((void**)&pWf1,  gbuf_wf1);
    cudaGetSymbolAddress((void**)&pWf2,  gbuf_wf2);

    cudaFuncSetAttribute(flash_kernel, cudaFuncAttributeMaxDynamicSharedMemorySize, FA_SMEM_BYTES);
    cudaFuncSetAttribute(tgemm<false,false>, cudaFuncAttributeMaxDynamicSharedMemorySize, TGEMM_SMEM);
    cudaFuncSetAttribute(tgemm<false,true >, cudaFuncAttributeMaxDynamicSharedMemorySize, TGEMM_SMEM);
    cudaFuncSetAttribute(tgemm<true ,false>, cudaFuncAttributeMaxDynamicSharedMemorySize, TGEMM_SMEM);

    // pre-round weights to tf32
    {
        int nWm  = Ln * 4 * 4 * Dn * Dn / 4;
        int nWf  = Ln * 2 * Dn * Fn / 4;
        cvt_tf32_kernel<<<(nWm + 255) / 256, 256>>>((const float4*)mha_w, (float4*)pWm, nWm);
        cvt_tf32_kernel<<<(nWf + 255) / 256, 256>>>((const float4*)ff_w1, (float4*)pWf1, nWf);
        cvt_tf32_kernel<<<(nWf + 255) / 256, 256>>>((const float4*)ff_w2, (float4*)pWf2, nWf);
    }

    embed_kernel<<<(2 * BSn * Dn) / 256, 256>>>(left_wrist, right_wrist, Wl, bl, Wr, br, pe, pX);

    const int gxP = Dn / BN, gyP = BSn / BM;                 // 4, 32
    const int totProj = gxP * gyP * 2;                       // 256
    const int totQKV  = gxP * gyP * 6;                       // 768
    const int gxF = Fn / BN;                                 // 16
    const int totFf1  = gxF * gyP * 2;                       // 1024
    const dim3 gFlash(Sn / 128, Bn * Hn, 2);

    for (int l = 0; l < Ln; l++) {
        const float* w_base  = pWm      + (long long)l * 4 * 4 * Dn * Dn;
        const float* b_base  = mha_b    + (long long)l * 4 * 4 * Dn;
        const float* lg_base = mha_ln_g + (long long)l * 4 * Dn;
        const float* lb_base = mha_ln_b + (long long)l * 4 * Dn;

        // ---- cross attention (blocks 0,1) ----
        tgemm<false,false><<<pg(totQKV), 128, TGEMM_SMEM>>>(pX, w_base, b_base, pQKV, nullptr,
            Dn, Dn, Dn, Dn, 3,
            0, RR, RR, 0,
            4LL * Dn * Dn, (long long)Dn * Dn, 4LL * Dn, (long long)Dn, RR,
            gxP, gyP, totQKV);
        flash_kernel<<<gFlash, 128, FA_SMEM_BYTES>>>(pQKV, pCtx);
        tgemm<false,true><<<pg(totProj), 128, TGEMM_SMEM>>>(pCtx, w_base + 3LL * Dn * Dn, b_base + 3LL * Dn, pO, pX,
            Dn, Dn, Dn, Dn, 1,
            0, 0, RR, 0,
            4LL * Dn * Dn, 0, 4LL * Dn, 0, RR,
            gxP, gyP, totProj);
        ln_kernel<<<2 * BSn, 128>>>(pO, lg_base, lb_base, pC);

        // ---- self attention (blocks 2,3) ----
        tgemm<false,false><<<pg(totQKV), 128, TGEMM_SMEM>>>(pC, w_base + 2LL * 4 * Dn * Dn, b_base + 2LL * 4 * Dn, pQKV, nullptr,
            Dn, Dn, Dn, Dn, 3,
            0, 0, RR, RR,
            4LL * Dn * Dn, (long long)Dn * Dn, 4LL * Dn, (long long)Dn, RR,
            gxP, gyP, totQKV);
        flash_kernel<<<gFlash, 128, FA_SMEM_BYTES>>>(pQKV, pCtx);
        tgemm<false,true><<<pg(totProj), 128, TGEMM_SMEM>>>(pCtx, w_base + (2LL * 4 + 3) * Dn * Dn, b_base + (2LL * 4 + 3) * Dn, pO, pC,
            Dn, Dn, Dn, Dn, 1,
            0, 0, RR, 0,
            4LL * Dn * Dn, 0, 4LL * Dn, 0, RR,
            gxP, gyP, totProj);
        ln_kernel<<<2 * BSn, 128>>>(pO, lg_base + 2 * Dn, lb_base + 2 * Dn, pX);

        // ---- FFNs ----
        tgemm<true,false><<<pg(totFf1), 128, TGEMM_SMEM>>>(pX, pWf1 + (long long)l * 2 * Dn * Fn, ff_b1 + (long long)l * 2 * Fn, pFfh, nullptr,
            Dn, Dn, Fn, Fn, 1,
            0, 0, RR, 0,
            (long long)Dn * Fn, 0, (long long)Fn, 0, (long long)BSn * Fn,
            gxF, gyP, totFf1);
        tgemm<false,true><<<pg(totProj), 128, TGEMM_SMEM>>>(pFfh, pWf2 + (long long)l * 2 * Fn * Dn, ff_b2 + (long long)l * 2 * Dn, pO, pX,
            Fn, Fn, Dn, Dn, 1,
            0, 0, (long long)BSn * Fn, 0,
            (long long)Fn * Dn, 0, (long long)Dn, 0, RR,
            gxP, gyP, totProj);
        ln_kernel<<<2 * BSn, 128>>>(pO, ff_ln_g + (long long)l * 2 * Dn, ff_ln_b + (long long)l * 2 * Dn, pX);
    }

    pool_kernel<<<64, 256>>>(pX, pFused);
    head_kernel<<<Bn, 512>>>(pFused, h1_w1, h1_b1, h1_w2, h1_b2, out);
    head_kernel<<<Bn, 512>>>(pFused, h2_w1, h2_b1, h2_w2, h2_b2, out + Bn * 2);
}

// round 16
// speedup vs baseline: 1.0167x; 1.0167x over previous
#include <cuda_runtime.h>
#include <cstdint>

// Problem constants
#define Bn   4
#define Sn   1024
#define INn  6
#define Dn   512
#define Hn   8
#define Ln   4
#define Fn   2048
#define DKn  64
#define BSn  (Bn * Sn)   // 4096 tokens
#define RR   ((long long)BSn * Dn)

// ---------------- scratch ----------------
__device__ float gbuf_x  [2 * BSn * Dn];
__device__ float gbuf_c  [2 * BSn * Dn];
__device__ float gbuf_qkv[6 * BSn * Dn];
__device__ float gbuf_ctx[2 * BSn * Dn];
__device__ float gbuf_o  [2 * BSn * Dn];
__device__ float gbuf_ffh[2 * BSn * Fn];
__device__ float gbuf_fused[Bn * 2 * Dn];
// tf32-pre-rounded weights
__device__ float gbuf_wm [Ln * 4 * 4 * Dn * Dn];
__device__ float gbuf_wf1[Ln * 2 * Dn * Fn];
__device__ float gbuf_wf2[Ln * 2 * Fn * Dn];

__device__ __forceinline__ float to_tf32(float x) {
    float r;
    asm("cvt.rna.tf32.f32 %0, %1;" : "=f"(r) : "f"(x));
    return r;
}

__device__ __forceinline__ float fast_ex2(float x) {
    float r;
    asm("ex2.approx.ftz.f32 %0, %1;" : "=f"(r) : "f"(x));
    return r;
}

__device__ __forceinline__ void mma_tf32(float* d, const uint32_t* a, const uint32_t* b) {
    asm volatile(
        "mma.sync.aligned.m16n8k8.row.col.f32.tf32.tf32.f32 "
        "{%0,%1,%2,%3}, {%4,%5,%6,%7}, {%8,%9}, {%0,%1,%2,%3};\n"
        : "+f"(d[0]), "+f"(d[1]), "+f"(d[2]), "+f"(d[3])
        : "r"(a[0]), "r"(a[1]), "r"(a[2]), "r"(a[3]),
          "r"(b[0]), "r"(b[1]));
}

#define CP_ASYNC16(dst, src) \
    asm volatile("cp.async.cg.shared.global [%0], [%1], 16;" :: "r"(dst), "l"(src))
#define CP_COMMIT() asm volatile("cp.async.commit_group;")

// ---------------- weight pre-round to tf32 ----------------
__global__ void cvt_tf32_kernel(const float4* __restrict__ in, float4* __restrict__ out, int n4)
{
    int i = blockIdx.x * 256 + threadIdx.x;
    if (i < n4) {
        float4 t = in[i];
        t.x = to_tf32(t.x); t.y = to_tf32(t.y);
        t.z = to_tf32(t.z); t.w = to_tf32(t.w);
        out[i] = t;
    }
}

// ---------------- embedding, both channels in one launch ----------------
__global__ void embed_kernel(const float* __restrict__ inL, const float* __restrict__ inR,
                             const float* __restrict__ WlP, const float* __restrict__ blP,
                             const float* __restrict__ WrP, const float* __restrict__ brP,
                             const float* __restrict__ pe, float* __restrict__ out)
{
    int idx = blockIdx.x * 256 + threadIdx.x;   // < 2*BSn*Dn
    int chan = (idx >= BSn * Dn) ? 1 : 0;
    int id = idx - chan * BSn * Dn;
    const float* in   = chan ? inR : inL;
    const float* W    = chan ? WrP : WlP;
    const float* bias = chan ? brP : blP;
    int d = id & (Dn - 1);
    int t = id >> 9;
    int s = t & (Sn - 1);
    float acc = bias[d] + pe[s * Dn + d];
#pragma unroll
    for (int i = 0; i < INn; i++)
        acc += in[t * INn + i] * W[i * Dn + d];
    out[idx] = to_tf32(acc);
}

// ---------------- TF32 GEMM (R13 config): 128x128x32, 4 warps x (64x64), 3-stage cp.async, 2 CTA/SM ----------------
#define BM 128
#define BN 128
#define BK 32
#define APAD 36
#define BPAD 136
#define A_STG (BM * APAD)
#define B_STG (BK * BPAD)
#define TGEMM_SMEM ((3 * A_STG + 3 * B_STG) * 4)   // 107520 bytes

template <bool RELU, bool RES>
__global__ __launch_bounds__(128, 2)
void tgemm(const float* __restrict__ A, const float* __restrict__ Bm,
           const float* __restrict__ bias, float* __restrict__ C,
           const float* __restrict__ Rres,
           int K, int lda, int ldb, int ldc, int zdiv,
           long long aQ0, long long aKV0, long long aQ1, long long aKV1,
           long long sBb, long long sBi, long long sBiasB, long long sBiasI,
           long long sC)
{
    extern __shared__ float sm[];
    float* As = sm;
    float* Bs = sm + 3 * A_STG;

    const int z = blockIdx.z;
    const int zb = z / zdiv, zi = z - zb * zdiv;
    A    += (zb == 0) ? (zi == 0 ? aQ0 : aKV0) : (zi == 0 ? aQ1 : aKV1);
    Bm   += zb * sBb + zi * sBi;
    bias += zb * sBiasB + zi * sBiasI;
    C    += (long long)z * sC;
    if (RES) Rres += (long long)z * sC;

    const int bm = blockIdx.y * BM;
    const int bn = blockIdx.x * BN;
    const int tid = threadIdx.x;
    const int lane = tid & 31;
    const int warp = tid >> 5;
    const int wm = (warp >> 1) * 64;
    const int wn = (warp & 1) * 64;
    const int g = lane >> 2;
    const int c = lane & 3;

    const int a_kc4 = tid & 7;
    const int a_row0 = tid >> 3;
    const int b_c4 = tid & 31;
    const int b_krow = tid >> 5;

    float acc[4][8][4];
#pragma unroll
    for (int i = 0; i < 4; i++)
#pragma unroll
        for (int j = 0; j < 8; j++)
#pragma unroll
            for (int q = 0; q < 4; q++) acc[i][j][q] = 0.f;

    const int NT = K / BK;

    auto prefetch = [&](int t) {
        const int k0 = t * BK;
        const int stage = t % 3;
        float* Ad = As + stage * A_STG;
        float* Bd = Bs + stage * B_STG;
#pragma unroll
        for (int v = 0; v < 8; v++) {
            int r = a_row0 + v * 16;
            uint32_t d = (uint32_t)__cvta_generic_to_shared(&Ad[r * APAD + a_kc4 * 4]);
            CP_ASYNC16(d, &A[(long long)(bm + r) * lda + k0 + a_kc4 * 4]);
        }
#pragma unroll
        for (int v = 0; v < 8; v++) {
            int r = b_krow + v * 4;
            uint32_t d = (uint32_t)__cvta_generic_to_shared(&Bd[r * BPAD + b_c4 * 4]);
            CP_ASYNC16(d, &Bm[(long long)(k0 + r) * ldb + bn + b_c4 * 4]);
        }
        CP_COMMIT();
    };

    prefetch(0);
    prefetch(1);

    for (int t = 0; t < NT; t++) {
        if (t + 1 < NT) asm volatile("cp.async.wait_group 1;");
        else            asm volatile("cp.async.wait_group 0;");
        __syncthreads();

        if (t + 2 < NT) prefetch(t + 2);

        const float* Ab = As + (t % 3) * A_STG;
        const float* Bb = Bs + (t % 3) * B_STG;
#pragma unroll
        for (int kk = 0; kk < BK; kk += 8) {
            uint32_t afr[4][4];
#pragma unroll
            for (int i = 0; i < 4; i++) {
                int m = wm + i * 16;
                afr[i][0] = *(const uint32_t*)&Ab[(m + g) * APAD + kk + c];
                afr[i][1] = *(const uint32_t*)&Ab[(m + g + 8) * APAD + kk + c];
                afr[i][2] = *(const uint32_t*)&Ab[(m + g) * APAD + kk + c + 4];
                afr[i][3] = *(const uint32_t*)&Ab[(m + g + 8) * APAD + kk + c + 4];
            }
            uint32_t bfr[8][2];
#pragma unroll
            for (int j = 0; j < 8; j++) {
                int n = wn + j * 8 + g;
                bfr[j][0] = *(const uint32_t*)&Bb[(kk + c) * BPAD + n];
                bfr[j][1] = *(const uint32_t*)&Bb[(kk + c + 4) * BPAD + n];
            }
#pragma unroll
            for (int i = 0; i < 4; i++)
#pragma unroll
                for (int j = 0; j < 8; j++)
                    mma_tf32(acc[i][j], afr[i], bfr[j]);
        }
        // no bottom sync: next iteration's top sync orders reads before prefetch(t+3)
    }

#pragma unroll
    for (int i = 0; i < 4; i++) {
        int row0 = bm + wm + i * 16 + g;
        int row1 = row0 + 8;
#pragma unroll
        for (int j = 0; j < 8; j++) {
            int col = bn + wn + j * 8 + 2 * c;
            float bv0 = bias[col];
            float bv1 = bias[col + 1];
            float2 o0, o1;
            o0.x = acc[i][j][0] + bv0;
            o0.y = acc[i][j][1] + bv1;
            o1.x = acc[i][j][2] + bv0;
            o1.y = acc[i][j][3] + bv1;
            if (RELU) {
                o0.x = fmaxf(o0.x, 0.f); o0.y = fmaxf(o0.y, 0.f);
                o1.x = fmaxf(o1.x, 0.f); o1.y = fmaxf(o1.y, 0.f);
            }
            if (RES) {
                float2 r0v = *(const float2*)&Rres[(long long)row0 * ldc + col];
                float2 r1v = *(const float2*)&Rres[(long long)row1 * ldc + col];
                o0.x += r0v.x; o0.y += r0v.y;
                o1.x += r1v.x; o1.y += r1v.y;
            }
            o0.x = to_tf32(o0.x); o0.y = to_tf32(o0.y);
            o1.x = to_tf32(o1.x); o1.y = to_tf32(o1.y);
            *(float2*)&C[(long long)row0 * ldc + col] = o0;
            *(float2*)&C[(long long)row1 * ldc + col] = o1;
        }
    }
}

// ---------------- flash attention: 4 warps x 32 q-rows, deferred softmax-sum reduction ----------------
#define FA_SMEM_BYTES ((128*68 + 2*64*68 + 2*64*72) * 4)

__global__ __launch_bounds__(128, 2)
void flash_kernel(const float* __restrict__ qkv, float* __restrict__ ctx)
{
    extern __shared__ float sm[];
    float* Qs = sm;                      // [128][68]
    float* Ks = sm + 128 * 68;           // [2][64][68]
    float* Vs = Ks + 2 * 64 * 68;        // [2][64][72]

    const int qt = blockIdx.x, bh = blockIdx.y, zb = blockIdx.z;
    const int b = bh >> 3, h = bh & 7;
    const float* Qg = qkv + (long long)zb * 3 * RR;
    const float* Kg = Qg + RR;
    const float* Vg = Qg + 2 * RR;
    const long long tq  = (long long)b * Sn + qt * 128;
    const long long tk0 = (long long)b * Sn;
    const int hc = h * DKn;

    const int tid = threadIdx.x, lane = tid & 31, warp = tid >> 5;
    const int g = lane >> 2, c = lane & 3;
    const int wrow = warp * 32;
    const int src0 = (lane & 28) | (c >> 1);
    const int src2 = src0 + 2;
    const bool codd = (c & 1) != 0;

    const float QS = 0.125f * 1.4426950408889634f;
#pragma unroll
    for (int i = 0; i < 16; i++) {
        int f = tid + i * 128, row = f >> 4, c4 = f & 15;
        float4 t = *(const float4*)&Qg[(tq + row) * Dn + hc + c4 * 4];
        t.x = to_tf32(t.x * QS); t.y = to_tf32(t.y * QS);
        t.z = to_tf32(t.z * QS); t.w = to_tf32(t.w * QS);
        *(float4*)&Qs[row * 68 + c4 * 4] = t;
    }

    auto prefetch = [&](int t, int buf) {
        const long long rbase = tk0 + t * 64;
#pragma unroll
        for (int i = 0; i < 8; i++) {
            int f = tid + i * 128, r = f >> 4, c4 = f & 15;
            const float* gk = &Kg[(rbase + r) * Dn + hc + c4 * 4];
            const float* gv = &Vg[(rbase + r) * Dn + hc + c4 * 4];
            uint32_t sk = (uint32_t)__cvta_generic_to_shared(&Ks[(buf * 64 + r) * 68 + c4 * 4]);
            uint32_t sv = (uint32_t)__cvta_generic_to_shared(&Vs[(buf * 64 + r) * 72 + c4 * 4]);
            CP_ASYNC16(sk, gk);
            CP_ASYNC16(sv, gv);
        }
        CP_COMMIT();
    };

    prefetch(0, 0);
    prefetch(1, 1);

    float l[2][2] = {{0.f, 0.f}, {0.f, 0.f}};
    float oacc[2][8][4];
#pragma unroll
    for (int st = 0; st < 2; st++)
#pragma unroll
        for (int j = 0; j < 8; j++)
#pragma unroll
            for (int q = 0; q < 4; q++) oacc[st][j][q] = 0.f;

    for (int t = 0; t < Sn / 64; t++) {
        if (t < Sn / 64 - 1) asm volatile("cp.async.wait_group 1;");
        else                 asm volatile("cp.async.wait_group 0;");
        __syncthreads();

        const float* Kb = &Ks[(t & 1) * 64 * 68];
        const float* Vb = &Vs[(t & 1) * 64 * 72];

        float sacc[2][8][4];
#pragma unroll
        for (int st = 0; st < 2; st++)
#pragma unroll
            for (int j = 0; j < 8; j++)
#pragma unroll
                for (int q = 0; q < 4; q++) sacc[st][j][q] = 0.f;
#pragma unroll
        for (int s = 0; s < 8; s++) {
            uint32_t af[2][4];
#pragma unroll
            for (int st = 0; st < 2; st++) {
                int r = wrow + st * 16;
                af[st][0] = *(const uint32_t*)&Qs[(r + g) * 68 + s * 8 + c];
                af[st][1] = *(const uint32_t*)&Qs[(r + g + 8) * 68 + s * 8 + c];
                af[st][2] = *(const uint32_t*)&Qs[(r + g) * 68 + s * 8 + c + 4];
                af[st][3] = *(const uint32_t*)&Qs[(r + g + 8) * 68 + s * 8 + c + 4];
            }
#pragma unroll
            for (int j = 0; j < 8; j++) {
                uint32_t bf[2];
                bf[0] = *(const uint32_t*)&Kb[(j * 8 + g) * 68 + s * 8 + c];
                bf[1] = *(const uint32_t*)&Kb[(j * 8 + g) * 68 + s * 8 + c + 4];
                mma_tf32(sacc[0][j], af[0], bf);
                mma_tf32(sacc[1][j], af[1], bf);
            }
        }

#pragma unroll
        for (int st = 0; st < 2; st++) {
            float ps0 = 0.f, ps1 = 0.f;
#pragma unroll
            for (int j = 0; j < 8; j++) {
                sacc[st][j][0] = fast_ex2(sacc[st][j][0]);
                sacc[st][j][1] = fast_ex2(sacc[st][j][1]);
                sacc[st][j][2] = fast_ex2(sacc[st][j][2]);
                sacc[st][j][3] = fast_ex2(sacc[st][j][3]);
                ps0 += sacc[st][j][0] + sacc[st][j][1];
                ps1 += sacc[st][j][2] + sacc[st][j][3];
            }
            l[st][0] += ps0;
            l[st][1] += ps1;
        }

#pragma unroll
        for (int s = 0; s < 8; s++) {
            uint32_t afp[2][4];
#pragma unroll
            for (int st = 0; st < 2; st++) {
                float v0 = __shfl_sync(0xffffffffu, sacc[st][s][0], src0);
                float v1 = __shfl_sync(0xffffffffu, sacc[st][s][1], src0);
                float v2 = __shfl_sync(0xffffffffu, sacc[st][s][2], src0);
                float v3 = __shfl_sync(0xffffffffu, sacc[st][s][3], src0);
                float w0 = __shfl_sync(0xffffffffu, sacc[st][s][0], src2);
                float w1 = __shfl_sync(0xffffffffu, sacc[st][s][1], src2);
                float w2 = __shfl_sync(0xffffffffu, sacc[st][s][2], src2);
                float w3 = __shfl_sync(0xffffffffu, sacc[st][s][3], src2);
                afp[st][0] = __float_as_uint(to_tf32(codd ? v1 : v0));
                afp[st][1] = __float_as_uint(to_tf32(codd ? v3 : v2));
                afp[st][2] = __float_as_uint(to_tf32(codd ? w1 : w0));
                afp[st][3] = __float_as_uint(to_tf32(codd ? w3 : w2));
            }
#pragma unroll
            for (int j = 0; j < 8; j++) {
                uint32_t bf[2];
                bf[0] = *(const uint32_t*)&Vb[(s * 8 + c) * 72 + j * 8 + g];
                bf[1] = *(const uint32_t*)&Vb[(s * 8 + c + 4) * 72 + j * 8 + g];
                mma_tf32(oacc[0][j], afp[0], bf);
                mma_tf32(oacc[1][j], afp[1], bf);
            }
        }

        __syncthreads();
        if (t + 2 < Sn / 64) prefetch(t + 2, t & 1);
    }

#pragma unroll
    for (int st = 0; st < 2; st++) {
#pragma unroll
        for (int hh = 0; hh < 2; hh++) {
            l[st][hh] += __shfl_xor_sync(0xffffffffu, l[st][hh], 1);
            l[st][hh] += __shfl_xor_sync(0xffffffffu, l[st][hh], 2);
        }
    }

    float* Co = ctx + (long long)zb * RR;
#pragma unroll
    for (int st = 0; st < 2; st++) {
        float inv0 = 1.f / l[st][0], inv1 = 1.f / l[st][1];
        int r = wrow + st * 16;
#pragma unroll
        for (int j = 0; j < 8; j++) {
            float2 o01, o23;
            o01.x = to_tf32(oacc[st][j][0] * inv0); o01.y = to_tf32(oacc[st][j][1] * inv0);
            o23.x = to_tf32(oacc[st][j][2] * inv1); o23.y = to_tf32(oacc[st][j][3] * inv1);
            *(float2*)&Co[(tq + r + g) * Dn + hc + j * 8 + 2 * c] = o01;
            *(float2*)&Co[(tq + r + g + 8) * Dn + hc + j * 8 + 2 * c] = o23;
        }
    }
}

// ---------------- layernorm (float4-vectorized I/O) ----------------
__global__ void ln_kernel(const float* __restrict__ x,
                          const float* __restrict__ g, const float* __restrict__ be,
                          float* __restrict__ out)
{
    long long row = blockIdx.x;
    const int chan = (row >= BSn) ? 1 : 0;
    const float* gp = g + chan * Dn;
    const float* bp = be + chan * Dn;
    const float* xp = x + row * Dn;
    int t = threadIdx.x;
    int lane = t & 31, warp = t >> 5;
    float4 v = *(const float4*)&xp[t * 4];
    float s  = v.x + v.y + v.z + v.w;
    float s2 = v.x * v.x + v.y * v.y + v.z * v.z + v.w * v.w;
#pragma unroll
    for (int o = 16; o > 0; o >>= 1) {
        s  += __shfl_xor_sync(0xffffffffu, s,  o);
        s2 += __shfl_xor_sync(0xffffffffu, s2, o);
    }
    __shared__ float ws[4], ws2[4];
    if (lane == 0) { ws[warp] = s; ws2[warp] = s2; }
    __syncthreads();
    float S  = ws[0] + ws[1] + ws[2] + ws[3];
    float S2 = ws2[0] + ws2[1] + ws2[2] + ws2[3];
    float mean = S * (1.f / Dn);
    float var  = S2 * (1.f / Dn) - mean * mean;
    float rstd = rsqrtf(var + 1e-5f);
    float4 gv = *(const float4*)&gp[t * 4];
    float4 bv = *(const float4*)&bp[t * 4];
    float4 o;
    o.x = to_tf32((v.x - mean) * rstd * gv.x + bv.x);
    o.y = to_tf32((v.y - mean) * rstd * gv.y + bv.y);
    o.z = to_tf32((v.z - mean) * rstd * gv.z + bv.z);
    o.w = to_tf32((v.w - mean) * rstd * gv.w + bv.w);
    *(float4*)&out[row * Dn + t * 4] = o;
}

// ---------------- pool (parallel over S) + heads ----------------
__global__ void pool_kernel(const float* __restrict__ x, float* __restrict__ fused)
{
    __shared__ float red[4][64];
    int blk = blockIdx.x;
    int bc = blk >> 3;
    int slab = blk & 7;
    int b = bc >> 1, chan = bc & 1;
    int t = threadIdx.x;
    int col = (t & 63) + slab * 64;
    int rg = t >> 6;
    const float* src = x + (long long)chan * RR + (long long)b * Sn * Dn + col;
    float s = 0.f;
    for (int r = rg * 256; r < (rg + 1) * 256; r++)
        s += src[(long long)r * Dn];
    red[rg][t & 63] = s;
    __syncthreads();
    if (rg == 0) {
        float tot = red[0][t] + red[1][t] + red[2][t] + red[3][t];
        fused[b * 2 * Dn + chan * Dn + col] = tot * (1.f / Sn);
    }
}

__global__ void head_kernel(const float* __restrict__ fused,
                            const float* __restrict__ w1, const float* __restrict__ b1,
                            const float* __restrict__ w2, const float* __restrict__ b2,
                            float* __restrict__ out)
{
    __shared__ float sf[2 * Dn];
    int b = blockIdx.x, t = threadIdx.x;
    sf[t]      = fused[b * 2 * Dn + t];
    sf[t + Dn] = fused[b * 2 * Dn + t + Dn];
    __syncthreads();
    float h = b1[t];
    for (int k = 0; k < 2 * Dn; k++)
        h += sf[k] * w1[k * Dn + t];
    h = fmaxf(h, 0.f);
    __shared__ float r0[512], r1[512];
    r0[t] = h * w2[t * 2 + 0];
    r1[t] = h * w2[t * 2 + 1];
    __syncthreads();
#pragma unroll
    for (int o = 256; o > 0; o >>= 1) {
        if (t < o) { r0[t] += r0[t + o]; r1[t] += r1[t + o]; }
        __syncthreads();
    }
    if (t == 0) {
        out[b * 2 + 0] = r0[0] + b2[0];
        out[b * 2 + 1] = r1[0] + b2[1];
    }
}

extern "C" void kernel_launch(void* const* d_in, const int* in_sizes, int n_in,
                              void* d_out, int out_size)
{
    const float* left_wrist  = (const float*)d_in[0];
    const float* right_wrist = (const float*)d_in[1];
    const float* Wl = (const float*)d_in[2];
    const float* bl = (const float*)d_in[3];
    const float* Wr = (const float*)d_in[4];
    const float* br = (const float*)d_in[5];
    const float* pe = (const float*)d_in[6];
    const float* mha_w    = (const float*)d_in[7];
    const float* mha_b    = (const float*)d_in[8];
    const float* mha_ln_g = (const float*)d_in[9];
    const float* mha_ln_b = (const float*)d_in[10];
    const float* ff_w1    = (const float*)d_in[11];
    const float* ff_b1    = (const float*)d_in[12];
    const float* ff_w2    = (const float*)d_in[13];
    const float* ff_b2    = (const float*)d_in[14];
    const float* ff_ln_g  = (const float*)d_in[15];
    const float* ff_ln_b  = (const float*)d_in[16];
    const float* h1_w1 = (const float*)d_in[17];
    const float* h1_b1 = (const float*)d_in[18];
    const float* h1_w2 = (const float*)d_in[19];
    const float* h1_b2 = (const float*)d_in[20];
    const float* h2_w1 = (const float*)d_in[21];
    const float* h2_b1 = (const float*)d_in[22];
    const float* h2_w2 = (const float*)d_in[23];
    const float* h2_b2 = (const float*)d_in[24];
    float* out = (float*)d_out;

    float *pX, *pC, *pQKV, *pCtx, *pO, *pFfh, *pFused, *pWm, *pWf1, *pWf2;
    cudaGetSymbolAddress((void**)&pX,    gbuf_x);
    cudaGetSymbolAddress((void**)&pC,    gbuf_c);
    cudaGetSymbolAddress((void**)&pQKV,  gbuf_qkv);
    cudaGetSymbolAddress((void**)&pCtx,  gbuf_ctx);
    cudaGetSymbolAddress((void**)&pO,    gbuf_o);
    cudaGetSymbolAddress((void**)&pFfh,  gbuf_ffh);
    cudaGetSymbolAddress((void**)&pFused, gbuf_fused);
    cudaGetSymbolAddress((void**)&pWm,   gbuf_wm);
    cudaGetSymbolAddress((void**)&pWf1,  gbuf_wf1);
    cudaGetSymbolAddress((void**)&pWf2,  gbuf_wf2);

    cudaFuncSetAttribute(flash_kernel, cudaFuncAttributeMaxDynamicSharedMemorySize, FA_SMEM_BYTES);
    cudaFuncSetAttribute(tgemm<false,false>, cudaFuncAttributeMaxDynamicSharedMemorySize, TGEMM_SMEM);
    cudaFuncSetAttribute(tgemm<false,true >, cudaFuncAttributeMaxDynamicSharedMemorySize, TGEMM_SMEM);
    cudaFuncSetAttribute(tgemm<true ,false>, cudaFuncAttributeMaxDynamicSharedMemorySize, TGEMM_SMEM);

    // pre-round weights to tf32
    {
        int nWm  = Ln * 4 * 4 * Dn * Dn / 4;
        int nWf  = Ln * 2 * Dn * Fn / 4;
        cvt_tf32_kernel<<<(nWm + 255) / 256, 256>>>((const float4*)mha_w, (float4*)pWm, nWm);
        cvt_tf32_kernel<<<(nWf + 255) / 256, 256>>>((const float4*)ff_w1, (float4*)pWf1, nWf);
        cvt_tf32_kernel<<<(nWf + 255) / 256, 256>>>((const float4*)ff_w2, (float4*)pWf2, nWf);
    }

    embed_kernel<<<(2 * BSn * Dn) / 256, 256>>>(left_wrist, right_wrist, Wl, bl, Wr, br, pe, pX);

    const dim3 gProj(Dn / BN, BSn / BM, 2);      // 4 x 32 x 2
    const dim3 gQKV(Dn / BN, BSn / BM, 6);       // 4 x 32 x 6
    const dim3 gFlash(Sn / 128, Bn * Hn, 2);
    const dim3 gFf1(Fn / BN, BSn / BM, 2);       // 16 x 32 x 2

    for (int l = 0; l < Ln; l++) {
        const float* w_base  = pWm      + (long long)l * 4 * 4 * Dn * Dn;
        const float* b_base  = mha_b    + (long long)l * 4 * 4 * Dn;
        const float* lg_base = mha_ln_g + (long long)l * 4 * Dn;
        const float* lb_base = mha_ln_b + (long long)l * 4 * Dn;

        // ---- cross attention (blocks 0,1) ----
        tgemm<false,false><<<gQKV, 128, TGEMM_SMEM>>>(pX, w_base, b_base, pQKV, nullptr,
            Dn, Dn, Dn, Dn, 3,
            0, RR, RR, 0,
            4LL * Dn * Dn, (long long)Dn * Dn, 4LL * Dn, (long long)Dn, RR);
        flash_kernel<<<gFlash, 128, FA_SMEM_BYTES>>>(pQKV, pCtx);
        tgemm<false,true><<<gProj, 128, TGEMM_SMEM>>>(pCtx, w_base + 3LL * Dn * Dn, b_base + 3LL * Dn, pO, pX,
            Dn, Dn, Dn, Dn, 1,
            0, 0, RR, 0,
            4LL * Dn * Dn, 0, 4LL * Dn, 0, RR);
        ln_kernel<<<2 * BSn, 128>>>(pO, lg_base, lb_base, pC);

        // ---- self attention (blocks 2,3) ----
        tgemm<false,false><<<gQKV, 128, TGEMM_SMEM>>>(pC, w_base + 2LL * 4 * Dn * Dn, b_base + 2LL * 4 * Dn, pQKV, nullptr,
            Dn, Dn, Dn, Dn, 3,
            0, 0, RR, RR,
            4LL * Dn * Dn, (long long)Dn * Dn, 4LL * Dn, (long long)Dn, RR);
        flash_kernel<<<gFlash, 128, FA_SMEM_BYTES>>>(pQKV, pCtx);
        tgemm<false,true><<<gProj, 128, TGEMM_SMEM>>>(pCtx, w_base + (2LL * 4 + 3) * Dn * Dn, b_base + (2LL * 4 + 3) * Dn, pO, pC,
            Dn, Dn, Dn, Dn, 1,
            0, 0, RR, 0,
            4LL * Dn * Dn, 0, 4LL * Dn, 0, RR);
        ln_kernel<<<2 * BSn, 128>>>(pO, lg_base + 2 * Dn, lb_base + 2 * Dn, pX);

        // ---- FFNs ----
        tgemm<true,false><<<gFf1, 128, TGEMM_SMEM>>>(pX, pWf1 + (long long)l * 2 * Dn * Fn, ff_b1 + (long long)l * 2 * Fn, pFfh, nullptr,
            Dn, Dn, Fn, Fn, 1,
            0, 0, RR, 0,
            (long long)Dn * Fn, 0, (long long)Fn, 0, (long long)BSn * Fn);
        tgemm<false,true><<<gProj, 128, TGEMM_SMEM>>>(pFfh, pWf2 + (long long)l * 2 * Fn * Dn, ff_b2 + (long long)l * 2 * Dn, pO, pX,
            Fn, Fn, Dn, Dn, 1,
            0, 0, (long long)BSn * Fn, 0,
            (long long)Fn * Dn, 0, (long long)Dn, 0, RR);
        ln_kernel<<<2 * BSn, 128>>>(pO, ff_ln_g + (long long)l * 2 * Dn, ff_ln_b + (long long)l * 2 * Dn, pX);
    }

    pool_kernel<<<64, 256>>>(pX, pFused);
    head_kernel<<<Bn, 512>>>(pFused, h1_w1, h1_b1, h1_w2, h1_b2, out);
    head_kernel<<<Bn, 512>>>(pFused, h2_w1, h2_b1, h2_w2, h2_b2, out + Bn * 2);
}